// round 16
// baseline (speedup 1.0000x reference)
#include <cuda_runtime.h>
#include <cuda_fp16.h>
#include <math.h>
#include <stdint.h>

// ---------------- problem constants ----------------
#define BATCH   32768
#define KCODES  4096
#define DLAT    64
#define HIDDEN  1024

// output layout (f32, reference return order, flattened+concat)
#define P_OFF    0
#define P_SIZE   (BATCH*40)
#define CP_OFF   (P_OFF + P_SIZE)
#define CP_SIZE  (BATCH*48)
#define W_OFF    (CP_OFF + CP_SIZE)
#define WA_SIZE  (BATCH*2)
#define A_OFF    (W_OFF + WA_SIZE)
#define LOSS_OFF (A_OFF + WA_SIZE)
#define IDX_OFF  (LOSS_OFF + 1)
#define PERP_OFF (IDX_OFF + BATCH)

#define HS 136           // VQ smem word stride (conflict-free)
#define AKP2 20          // BK32 A smem word stride (16 used + 4 pad)
#define BNP 136          // B smem word stride

// ---------------- scratch (__device__ globals; no allocation allowed) ----------------
__device__ float  g_z  [BATCH*DLAT];
__device__ int    g_idx[BATCH];
__device__ float  g_counts[KCODES];
__device__ float  g_loss;
__device__ float  g_enorm[KCODES];
__device__ float  g_hb [128];
__device__ float  g_b3p[128];             // padded b3
// fp16-split packed operands (encoder + VQ); x/W1 padded K 784->800
__device__ uint32_t g_xH [BATCH*400];
__device__ uint32_t g_xL [BATCH*400];
__device__ uint32_t g_w1H[400*256];
__device__ uint32_t g_w1L[400*256];
__device__ uint32_t g_h1H[BATCH*128];
__device__ uint32_t g_h1L[BATCH*128];
__device__ uint32_t g_w2H[128*256];
__device__ uint32_t g_w2L[128*256];
__device__ uint32_t g_h2H[BATCH*128];
__device__ uint32_t g_h2L[BATCH*128];
__device__ uint32_t g_w3H[128*128];       // W3 padded [kp=128][n=128]
__device__ uint32_t g_w3L[128*128];
__device__ uint32_t g_zHiT[32*BATCH];
__device__ uint32_t g_zLoT[32*BATCH];
__device__ uint32_t g_eHiT[32*KCODES];
__device__ uint32_t g_eLoT[32*KCODES];
// fp16 hi-only packed (decoder)
__device__ uint32_t g_zqH [BATCH*32];
__device__ uint32_t g_dW1H[32*HIDDEN];
__device__ uint32_t g_d1H [BATCH*512];
__device__ uint32_t g_dW2H[512*HIDDEN];
__device__ uint32_t g_d2H [BATCH*512];
__device__ uint32_t g_hwH [512*128];

// ---------------- activations ----------------
#define ACT_NONE 0
#define ACT_LEAKY 1
#define ACT_SELU 2
#define ACT_HEAD 3

__device__ __forceinline__ float sigmoidf_(float x){ return 1.0f/(1.0f+expf(-x)); }

template<int ACT>
__device__ __forceinline__ float apply_act(float v, int col){
    if (ACT == ACT_LEAKY) return v > 0.0f ? v : 0.2f*v;
    if (ACT == ACT_SELU){
        const float a = 1.6732632423543772f, s = 1.0507009873554805f;
        return v > 0.0f ? s*v : s*a*(expf(v)-1.0f);
    }
    if (ACT == ACT_HEAD){
        if (col < 40) return tanhf(v)*12.0f + 14.0f;
        if (col < 42) return sigmoidf_(v)*2.0f + 1.0f;
        return sigmoidf_(v);
    }
    return v;
}

// ---------------- fp16 pack helpers ----------------
__device__ __forceinline__ void fp16_split_pack(float x0, float x1,
                                                uint32_t& hi, uint32_t& lo){
    __half h0 = __float2half_rn(x0), h1 = __float2half_rn(x1);
    __half l0 = __float2half_rn(x0 - __half2float(h0));
    __half l1 = __float2half_rn(x1 - __half2float(h1));
    __half2 hh = __halves2half2(h0, h1);
    __half2 ll = __halves2half2(l0, l1);
    hi = *(uint32_t*)&hh;
    lo = *(uint32_t*)&ll;
}
__device__ __forceinline__ uint32_t fp16_pack_hi(float x0, float x1){
    __half2 hh = __halves2half2(__float2half_rn(x0), __float2half_rn(x1));
    return *(uint32_t*)&hh;
}

// D += A*B, m16n8k16 fp16 (fp32 accum)
__device__ __forceinline__ void mma16(float* c, const uint32_t* a, const uint32_t* b){
    asm volatile(
        "mma.sync.aligned.m16n8k16.row.col.f32.f16.f16.f32 "
        "{%0,%1,%2,%3}, {%4,%5,%6,%7}, {%8,%9}, {%0,%1,%2,%3};\n"
        : "+f"(c[0]), "+f"(c[1]), "+f"(c[2]), "+f"(c[3])
        : "r"(a[0]), "r"(a[1]), "r"(a[2]), "r"(a[3]), "r"(b[0]), "r"(b[1]));
}

// ---------------- cp.async helpers ----------------
__device__ __forceinline__ void cpasync16(void* dst_smem, const void* src){
    uint32_t s = (uint32_t)__cvta_generic_to_shared(dst_smem);
    asm volatile("cp.async.cg.shared.global [%0], [%1], 16;\n" :: "r"(s), "l"(src));
}
__device__ __forceinline__ void cpasync_commit(){ asm volatile("cp.async.commit_group;\n"); }
template<int NN>
__device__ __forceinline__ void cpasync_wait(){ asm volatile("cp.async.wait_group %0;\n" :: "n"(NN)); }

// ---------------- x pack (wide, float4/thread, K padded 784->800) ----------------
__global__ void pack_rowsA4(const float* __restrict__ src,
                            uint32_t* __restrict__ hiA, uint32_t* __restrict__ loA){
    int i = blockIdx.x * 256 + threadIdx.x;     // quad index; 200 quads per row
    if (i >= BATCH*200) return;
    int row = i / 200, q = i - row*200;
    float4 v = make_float4(0.f, 0.f, 0.f, 0.f);
    if (q < 196) v = *(const float4*)(src + (size_t)row*784 + q*4);
    uint32_t h0, l0, h1, l1;
    fp16_split_pack(v.x, v.y, h0, l0);
    fp16_split_pack(v.z, v.w, h1, l1);
    ((uint2*)hiA)[i] = make_uint2(h0, h1);
    ((uint2*)loA)[i] = make_uint2(l0, l1);
}

// ---------------- mega setup: all weight packs + scalars in ONE launch ----------------
#define S_ZERO   (KCODES + 1)                 // counts + loss
#define S_ENORM  KCODES
#define S_W1     (400*256)
#define S_W2     (128*256)
#define S_W3     (128*128)
#define S_EMBT   (32*KCODES)
#define S_DW1    (32*HIDDEN)
#define S_DW2    (512*HIDDEN)
#define S_HEAD   (512*128)
#define O_ENORM  S_ZERO
#define O_W1     (O_ENORM + S_ENORM)
#define O_W2     (O_W1 + S_W1)
#define O_W3     (O_W2 + S_W2)
#define O_EMBT   (O_W3 + S_W3)
#define O_DW1    (O_EMBT + S_EMBT)
#define O_DW2    (O_DW1 + S_DW1)
#define O_HEAD   (O_DW2 + S_DW2)
#define S_TOTAL  (O_HEAD + S_HEAD)

__device__ __forceinline__ float head_w(const float* pW, const float* wW,
                                        const float* aW, int k, int col){
    if (col < 40) return pW[k*40 + col];
    if (col < 42) return wW[k*2 + (col-40)];
    if (col < 44) return aW[k*2 + (col-42)];
    return 0.0f;
}

__global__ void mega_setup(
    const float* __restrict__ W1, const float* __restrict__ W2,
    const float* __restrict__ W3, const float* __restrict__ b3,
    const float* __restrict__ emb,
    const float* __restrict__ dW1, const float* __restrict__ dW2,
    const float* __restrict__ pW, const float* __restrict__ pb,
    const float* __restrict__ wW, const float* __restrict__ wb,
    const float* __restrict__ aW, const float* __restrict__ ab,
    float* __restrict__ counts, float* __restrict__ loss,
    float* __restrict__ enorm, float* __restrict__ b3p, float* __restrict__ hb,
    uint32_t* __restrict__ w1H, uint32_t* __restrict__ w1L,
    uint32_t* __restrict__ w2H, uint32_t* __restrict__ w2L,
    uint32_t* __restrict__ w3H, uint32_t* __restrict__ w3L,
    uint32_t* __restrict__ eHiT, uint32_t* __restrict__ eLoT,
    uint32_t* __restrict__ dW1H, uint32_t* __restrict__ dW2H,
    uint32_t* __restrict__ hwH)
{
    int gi = blockIdx.x * 256 + threadIdx.x;
    if (gi >= S_TOTAL) return;

    if (gi < S_ZERO){
        if (gi < KCODES) counts[gi] = 0.0f; else loss[0] = 0.0f;
    } else if (gi < O_W1){
        int k = gi - O_ENORM;
        const float4* e = (const float4*)(emb + (size_t)k * DLAT);
        float s = 0.0f;
        #pragma unroll
        for (int q = 0; q < 16; q++){
            float4 v = e[q];
            s += v.x*v.x + v.y*v.y + v.z*v.z + v.w*v.w;
        }
        enorm[k] = s;
    } else if (gi < O_W2){
        int i = gi - O_W1;                 // W1 pack [kp=400][n=256], kp>=392 zero
        int kp = i >> 8, n = i & 255;
        float x0 = 0.0f, x1 = 0.0f;
        if (kp < 392){
            x0 = W1[(size_t)(2*kp)*256 + n];
            x1 = W1[(size_t)(2*kp+1)*256 + n];
        }
        uint32_t hi, lo;
        fp16_split_pack(x0, x1, hi, lo);
        w1H[i] = hi; w1L[i] = lo;
    } else if (gi < O_W3){
        int i = gi - O_W2;                 // W2 pack [kp=128][n=256]
        int kp = i >> 8, n = i & 255;
        uint32_t hi, lo;
        fp16_split_pack(W2[(size_t)(2*kp)*256 + n], W2[(size_t)(2*kp+1)*256 + n], hi, lo);
        w2H[i] = hi; w2L[i] = lo;
    } else if (gi < O_EMBT){
        int i = gi - O_W3;                 // W3 padded pack [kp=128][n=128]
        int kp = i >> 7, n = i & 127;
        float x0 = 0.0f, x1 = 0.0f;
        if (n < 64){
            x0 = W3[(size_t)(2*kp)*64 + n];
            x1 = W3[(size_t)(2*kp+1)*64 + n];
        }
        uint32_t hi, lo;
        fp16_split_pack(x0, x1, hi, lo);
        w3H[i] = hi; w3L[i] = lo;
        if (i < 128) b3p[i] = (i < 64) ? b3[i] : 0.0f;
    } else if (gi < O_DW1){
        int i = gi - O_EMBT;               // embT pack [dp=32][code]
        int dp = i >> 12, c = i & (KCODES-1);
        uint32_t hi, lo;
        fp16_split_pack(emb[(size_t)c*DLAT + 2*dp], emb[(size_t)c*DLAT + 2*dp + 1], hi, lo);
        eHiT[i] = hi; eLoT[i] = lo;
    } else if (gi < O_DW2){
        int i = gi - O_DW1;                // dW1 hi pack [kp=32][n=1024]
        int kp = i >> 10, n = i & 1023;
        dW1H[i] = fp16_pack_hi(dW1[(size_t)(2*kp)*HIDDEN + n], dW1[(size_t)(2*kp+1)*HIDDEN + n]);
    } else if (gi < O_HEAD){
        int i = gi - O_DW2;                // dW2 hi pack [kp=512][n=1024]
        int kp = i >> 10, n = i & 1023;
        dW2H[i] = fp16_pack_hi(dW2[(size_t)(2*kp)*HIDDEN + n], dW2[(size_t)(2*kp+1)*HIDDEN + n]);
    } else {
        int i = gi - O_HEAD;               // head hi pack (direct) [kp=512][n=128]
        int kp = i >> 7, n = i & 127;
        float x0 = head_w(pW, wW, aW, 2*kp,   n);
        float x1 = head_w(pW, wW, aW, 2*kp+1, n);
        hwH[i] = fp16_pack_hi(x0, x1);
        if (i < 128){
            float v = 0.0f;
            if (i < 40)      v = pb[i];
            else if (i < 42) v = wb[i-40];
            else if (i < 44) v = ab[i-42];
            hb[i] = v;
        }
    }
}

// ============================================================================
// fp16-split GEMM: 3-product hi/lo. A [m][kp], B [kp][n]. BK=32.
// OUTPACK: 0 = fp32 C; 1 = packed hi/lo C;
//          2 = fp32 z (cols<64) + transposed hi/lo packs zHiT/zLoT [dp][b]
// ============================================================================
template<int ACT, int OUTPACK>
__global__ void __launch_bounds__(256, 2) mma_gemm_f16(
    const uint32_t* __restrict__ AH, const uint32_t* __restrict__ AL,
    const uint32_t* __restrict__ BH, const uint32_t* __restrict__ BL,
    const float* __restrict__ bias, float* __restrict__ C,
    uint32_t* __restrict__ CH, uint32_t* __restrict__ CL,
    int M, int N, int K)
{
    __shared__ uint32_t AsH[2][128][AKP2], AsL[2][128][AKP2];
    __shared__ uint32_t BsH[2][16][BNP],   BsL[2][16][BNP];

    const int tid  = threadIdx.x;
    const int lane = tid & 31, warp = tid >> 5;
    const int wm = (warp & 1) * 64, wn = (warp >> 1) * 32;
    const int bm = blockIdx.y * 128, bn = blockIdx.x * 128;
    const int g = lane >> 2, tg = lane & 3;
    const int KP = K >> 1;

    float acc[4][4][4];
    #pragma unroll
    for (int i = 0; i < 4; i++)
        #pragma unroll
        for (int j = 0; j < 4; j++)
            #pragma unroll
            for (int q = 0; q < 4; q++) acc[i][j][q] = 0.0f;

    const int ar = tid >> 1, ac = (tid & 1) * 8;
    const int br = tid >> 4, bc = (tid & 15) * 8;
    const uint32_t* AHp = AH + (size_t)(bm + ar) * KP + ac;
    const uint32_t* ALp = AL + (size_t)(bm + ar) * KP + ac;
    const uint32_t* BHp = BH + (size_t)br * N + bn + bc;
    const uint32_t* BLp = BL + (size_t)br * N + bn + bc;

    const int ntiles = K >> 5;   // 16 kp per tile

    #define COPY_F16(kt, buf) do { \
        cpasync16(&AsH[buf][ar][ac],   AHp + (size_t)(kt)*16); \
        cpasync16(&AsH[buf][ar][ac+4], AHp + (size_t)(kt)*16 + 4); \
        cpasync16(&AsL[buf][ar][ac],   ALp + (size_t)(kt)*16); \
        cpasync16(&AsL[buf][ar][ac+4], ALp + (size_t)(kt)*16 + 4); \
        cpasync16(&BsH[buf][br][bc],   BHp + (size_t)(kt)*16*N); \
        cpasync16(&BsH[buf][br][bc+4], BHp + (size_t)(kt)*16*N + 4); \
        cpasync16(&BsL[buf][br][bc],   BLp + (size_t)(kt)*16*N); \
        cpasync16(&BsL[buf][br][bc+4], BLp + (size_t)(kt)*16*N + 4); \
        cpasync_commit(); \
    } while (0)

    COPY_F16(0, 0);

    for (int i = 0; i < ntiles; i++){
        int buf = i & 1;
        if (i + 1 < ntiles){
            COPY_F16(i + 1, buf ^ 1);
            cpasync_wait<1>();
        } else {
            cpasync_wait<0>();
        }
        __syncthreads();

        #pragma unroll
        for (int kb = 0; kb < 2; kb++){
            uint32_t ah[4][4], al[4][4];
            #pragma unroll
            for (int mt = 0; mt < 4; mt++){
                int m = wm + mt*16 + g;
                ah[mt][0] = AsH[buf][m  ][kb*8+tg];
                ah[mt][1] = AsH[buf][m+8][kb*8+tg];
                ah[mt][2] = AsH[buf][m  ][kb*8+tg+4];
                ah[mt][3] = AsH[buf][m+8][kb*8+tg+4];
                al[mt][0] = AsL[buf][m  ][kb*8+tg];
                al[mt][1] = AsL[buf][m+8][kb*8+tg];
                al[mt][2] = AsL[buf][m  ][kb*8+tg+4];
                al[mt][3] = AsL[buf][m+8][kb*8+tg+4];
            }
            #pragma unroll
            for (int nt = 0; nt < 4; nt++){
                int n = wn + nt*8 + g;
                uint32_t bh[2] = { BsH[buf][kb*8+tg][n], BsH[buf][kb*8+tg+4][n] };
                uint32_t bl[2] = { BsL[buf][kb*8+tg][n], BsL[buf][kb*8+tg+4][n] };
                #pragma unroll
                for (int mt = 0; mt < 4; mt++) mma16(acc[mt][nt], ah[mt], bh);
                #pragma unroll
                for (int mt = 0; mt < 4; mt++) mma16(acc[mt][nt], al[mt], bh);
                #pragma unroll
                for (int mt = 0; mt < 4; mt++) mma16(acc[mt][nt], ah[mt], bl);
            }
        }
        __syncthreads();
    }
    #undef COPY_F16

    #pragma unroll
    for (int mt = 0; mt < 4; mt++){
        #pragma unroll
        for (int nt = 0; nt < 4; nt++){
            int row = bm + wm + mt*16 + g;
            int col = bn + wn + nt*8 + 2*tg;
            float bs0 = bias[col], bs1 = bias[col+1];
            float v00 = apply_act<ACT>(acc[mt][nt][0] + bs0, col);
            float v01 = apply_act<ACT>(acc[mt][nt][1] + bs1, col+1);
            float v10 = apply_act<ACT>(acc[mt][nt][2] + bs0, col);
            float v11 = apply_act<ACT>(acc[mt][nt][3] + bs1, col+1);
            if (OUTPACK == 1){
                int w = col >> 1;
                int NP = N >> 1;
                uint32_t h0, l0, h1, l1;
                fp16_split_pack(v00, v01, h0, l0);
                fp16_split_pack(v10, v11, h1, l1);
                CH[(size_t)row*NP + w]     = h0;
                CL[(size_t)row*NP + w]     = l0;
                CH[(size_t)(row+8)*NP + w] = h1;
                CL[(size_t)(row+8)*NP + w] = l1;
            } else if (OUTPACK == 2){
                if (col < DLAT){
                    *(float2*)&C[(size_t)row*DLAT + col]     = make_float2(v00, v01);
                    *(float2*)&C[(size_t)(row+8)*DLAT + col] = make_float2(v10, v11);
                    int dp = col >> 1;
                    uint32_t h0, l0, h1, l1;
                    fp16_split_pack(v00, v01, h0, l0);
                    fp16_split_pack(v10, v11, h1, l1);
                    CH[(size_t)dp*BATCH + row]     = h0;
                    CL[(size_t)dp*BATCH + row]     = l0;
                    CH[(size_t)dp*BATCH + row + 8] = h1;
                    CL[(size_t)dp*BATCH + row + 8] = l1;
                }
            } else {
                *(float2*)&C[(size_t)row*N + col]     = make_float2(v00, v01);
                *(float2*)&C[(size_t)(row+8)*N + col] = make_float2(v10, v11);
            }
        }
    }
}

// ============================================================================
// fp16 hi-only GEMM (decoder + head): 1-product, BK=32.
// OUTPACK: 0 = fp32 C; 1 = packed hi C; 3 = fused output packing (head)
// ============================================================================
template<int ACT, int OUTPACK>
__global__ void __launch_bounds__(256, 2) mma_gemm_h16(
    const uint32_t* __restrict__ AH, const uint32_t* __restrict__ BH,
    const float* __restrict__ bias, float* __restrict__ C,
    uint32_t* __restrict__ CH,
    int M, int N, int K)
{
    __shared__ uint32_t AsH[2][128][AKP2];
    __shared__ uint32_t BsH[2][16][BNP];

    const int tid  = threadIdx.x;
    const int lane = tid & 31, warp = tid >> 5;
    const int wm = (warp & 1) * 64, wn = (warp >> 1) * 32;
    const int bm = blockIdx.y * 128, bn = blockIdx.x * 128;
    const int g = lane >> 2, tg = lane & 3;
    const int KP = K >> 1;

    float acc[4][4][4];
    #pragma unroll
    for (int i = 0; i < 4; i++)
        #pragma unroll
        for (int j = 0; j < 4; j++)
            #pragma unroll
            for (int q = 0; q < 4; q++) acc[i][j][q] = 0.0f;

    const int ar = tid >> 1, ac = (tid & 1) * 8;
    const int br = tid >> 4, bc = (tid & 15) * 8;
    const uint32_t* AHp = AH + (size_t)(bm + ar) * KP + ac;
    const uint32_t* BHp = BH + (size_t)br * N + bn + bc;

    const int ntiles = K >> 5;   // 16 kp per tile

    #define COPY_H16(kt, buf) do { \
        cpasync16(&AsH[buf][ar][ac],   AHp + (size_t)(kt)*16); \
        cpasync16(&AsH[buf][ar][ac+4], AHp + (size_t)(kt)*16 + 4); \
        cpasync16(&BsH[buf][br][bc],   BHp + (size_t)(kt)*16*N); \
        cpasync16(&BsH[buf][br][bc+4], BHp + (size_t)(kt)*16*N + 4); \
        cpasync_commit(); \
    } while (0)

    COPY_H16(0, 0);

    for (int i = 0; i < ntiles; i++){
        int buf = i & 1;
        if (i + 1 < ntiles){
            COPY_H16(i + 1, buf ^ 1);
            cpasync_wait<1>();
        } else {
            cpasync_wait<0>();
        }
        __syncthreads();

        #pragma unroll
        for (int kb = 0; kb < 2; kb++){
            uint32_t ah[4][4];
            #pragma unroll
            for (int mt = 0; mt < 4; mt++){
                int m = wm + mt*16 + g;
                ah[mt][0] = AsH[buf][m  ][kb*8+tg];
                ah[mt][1] = AsH[buf][m+8][kb*8+tg];
                ah[mt][2] = AsH[buf][m  ][kb*8+tg+4];
                ah[mt][3] = AsH[buf][m+8][kb*8+tg+4];
            }
            #pragma unroll
            for (int nt = 0; nt < 4; nt++){
                int n = wn + nt*8 + g;
                uint32_t bh[2] = { BsH[buf][kb*8+tg][n], BsH[buf][kb*8+tg+4][n] };
                #pragma unroll
                for (int mt = 0; mt < 4; mt++) mma16(acc[mt][nt], ah[mt], bh);
            }
        }
        __syncthreads();
    }
    #undef COPY_H16

    #pragma unroll
    for (int mt = 0; mt < 4; mt++){
        #pragma unroll
        for (int nt = 0; nt < 4; nt++){
            int row = bm + wm + mt*16 + g;
            int col = bn + wn + nt*8 + 2*tg;
            float bs0 = bias[col], bs1 = bias[col+1];
            float v00 = apply_act<ACT>(acc[mt][nt][0] + bs0, col);
            float v01 = apply_act<ACT>(acc[mt][nt][1] + bs1, col+1);
            float v10 = apply_act<ACT>(acc[mt][nt][2] + bs0, col);
            float v11 = apply_act<ACT>(acc[mt][nt][3] + bs1, col+1);
            if (OUTPACK == 1){
                int w = col >> 1;
                int NP = N >> 1;
                CH[(size_t)row*NP + w]     = fp16_pack_hi(v00, v01);
                CH[(size_t)(row+8)*NP + w] = fp16_pack_hi(v10, v11);
            } else if (OUTPACK == 3){
                // fused output packing (head): col even, valid cols < 44
                if (col < 40){
                    int p = col / 20, rem = col - p*20;
                    int q = rem >> 1;
                    *(float2*)&C[P_OFF + (size_t)row*40 + col]     = make_float2(v00, v01);
                    *(float2*)&C[P_OFF + (size_t)(row+8)*40 + col] = make_float2(v10, v11);
                    #pragma unroll
                    for (int sg = 0; sg < 3; sg++){
                        int j = q - 3*sg;
                        if (j >= 0 && j < 4){
                            size_t o = (size_t)p*24 + sg*8 + j*2;
                            *(float2*)&C[CP_OFF + (size_t)row*48 + o]     = make_float2(v00, v01);
                            *(float2*)&C[CP_OFF + (size_t)(row+8)*48 + o] = make_float2(v10, v11);
                        }
                    }
                } else if (col == 40){
                    *(float2*)&C[W_OFF + (size_t)row*2]     = make_float2(v00, v01);
                    *(float2*)&C[W_OFF + (size_t)(row+8)*2] = make_float2(v10, v11);
                } else if (col == 42){
                    *(float2*)&C[A_OFF + (size_t)row*2]     = make_float2(v00, v01);
                    *(float2*)&C[A_OFF + (size_t)(row+8)*2] = make_float2(v10, v11);
                }
            } else {
                *(float2*)&C[(size_t)row*N + col]     = make_float2(v00, v01);
                *(float2*)&C[(size_t)(row+8)*N + col] = make_float2(v10, v11);
            }
        }
    }
}

// ---------------- VQ argmin: fp16-split m16n8k16, pre-packed operands ----------------
__global__ void __launch_bounds__(256, 2) vq_argmin_f16(
    const uint32_t* __restrict__ zHiT, const uint32_t* __restrict__ zLoT,
    const uint32_t* __restrict__ eHiT, const uint32_t* __restrict__ eLoT,
    const float* __restrict__ enorm, int* __restrict__ idx_out)
{
    __shared__ uint32_t ZH[32][HS], ZL[32][HS];
    __shared__ uint32_t EH[2][32][HS], EL[2][32][HS];

    const int tid  = threadIdx.x;
    const int lane = tid & 31, warp = tid >> 5;
    const int wm = (warp & 1) * 64, wn = (warp >> 1) * 32;
    const int bm = blockIdx.x * 128;
    const int g = lane >> 2, tg = lane & 3;

    {
        #pragma unroll
        for (int j = 0; j < 4; j++){
            int unit = j*256 + tid;
            int dp = unit >> 5, u = unit & 31;
            cpasync16(&ZH[dp][u*4], zHiT + (size_t)dp*BATCH + bm + u*4);
            cpasync16(&ZL[dp][u*4], zLoT + (size_t)dp*BATCH + bm + u*4);
        }
        cpasync_commit();
    }

    #define COPY_EP(c0_, buf_) do { \
        _Pragma("unroll") \
        for (int j = 0; j < 4; j++){ \
            int unit = j*256 + tid; \
            int dp_ = unit >> 5, u_ = unit & 31; \
            cpasync16(&EH[buf_][dp_][u_*4], eHiT + (size_t)dp_*KCODES + (c0_) + u_*4); \
            cpasync16(&EL[buf_][dp_][u_*4], eLoT + (size_t)dp_*KCODES + (c0_) + u_*4); \
        } \
        cpasync_commit(); \
    } while (0)

    float mv[8]; int mi[8];
    #pragma unroll
    for (int s = 0; s < 8; s++){ mv[s] = INFINITY; mi[s] = 0; }

    COPY_EP(0, 0);

    for (int ch = 0; ch < KCODES/128; ch++){
        int c0 = ch * 128;
        int buf = ch & 1;
        if (ch + 1 < KCODES/128){
            COPY_EP(c0 + 128, buf ^ 1);
            cpasync_wait<1>();
        } else {
            cpasync_wait<0>();
        }
        __syncthreads();

        float acc[4][4][4];
        #pragma unroll
        for (int i = 0; i < 4; i++)
            #pragma unroll
            for (int j = 0; j < 4; j++)
                #pragma unroll
                for (int q = 0; q < 4; q++) acc[i][j][q] = 0.0f;

        #pragma unroll
        for (int kb = 0; kb < 4; kb++){
            uint32_t ah[4][4], al[4][4];
            #pragma unroll
            for (int mt = 0; mt < 4; mt++){
                int m = wm + mt*16 + g;
                ah[mt][0] = ZH[kb*8+tg  ][m];
                ah[mt][1] = ZH[kb*8+tg  ][m+8];
                ah[mt][2] = ZH[kb*8+tg+4][m];
                ah[mt][3] = ZH[kb*8+tg+4][m+8];
                al[mt][0] = ZL[kb*8+tg  ][m];
                al[mt][1] = ZL[kb*8+tg  ][m+8];
                al[mt][2] = ZL[kb*8+tg+4][m];
                al[mt][3] = ZL[kb*8+tg+4][m+8];
            }
            #pragma unroll
            for (int nt = 0; nt < 4; nt++){
                int n = wn + nt*8 + g;
                uint32_t bh[2] = { EH[buf][kb*8+tg][n], EH[buf][kb*8+tg+4][n] };
                uint32_t bl[2] = { EL[buf][kb*8+tg][n], EL[buf][kb*8+tg+4][n] };
                #pragma unroll
                for (int mt = 0; mt < 4; mt++) mma16(acc[mt][nt], ah[mt], bh);
                #pragma unroll
                for (int mt = 0; mt < 4; mt++) mma16(acc[mt][nt], al[mt], bh);
                #pragma unroll
                for (int mt = 0; mt < 4; mt++) mma16(acc[mt][nt], ah[mt], bl);
            }
        }

        #pragma unroll
        for (int nt = 0; nt < 4; nt++){
            int nc = wn + nt*8 + 2*tg;
            float e0 = __ldg(enorm + c0 + nc);
            float e1 = __ldg(enorm + c0 + nc + 1);
            int code = c0 + nc;
            #pragma unroll
            for (int mt = 0; mt < 4; mt++){
                float d00 = e0 - 2.0f*acc[mt][nt][0];
                float d01 = e1 - 2.0f*acc[mt][nt][1];
                float d10 = e0 - 2.0f*acc[mt][nt][2];
                float d11 = e1 - 2.0f*acc[mt][nt][3];
                int s0 = mt*2, s1 = mt*2 + 1;
                if (d00 < mv[s0]){ mv[s0] = d00; mi[s0] = code;   }
                if (d01 < mv[s0]){ mv[s0] = d01; mi[s0] = code+1; }
                if (d10 < mv[s1]){ mv[s1] = d10; mi[s1] = code;   }
                if (d11 < mv[s1]){ mv[s1] = d11; mi[s1] = code+1; }
            }
        }
        __syncthreads();
    }
    #undef COPY_EP

    float* rv = (float*)&EH[0][0][0];
    int*   ri = ((int*)rv) + 16*128;
    int cand = (warp >> 1) * 4 + tg;
    #pragma unroll
    for (int s = 0; s < 8; s++){
        int r = wm + (s >> 1)*16 + g + (s & 1)*8;
        rv[cand*128 + r] = mv[s];
        ri[cand*128 + r] = mi[s];
    }
    __syncthreads();
    if (tid < 128){
        float bv = INFINITY; int bi = 0x7fffffff;
        #pragma unroll
        for (int t = 0; t < 16; t++){
            float v = rv[t*128 + tid];
            int c = ri[t*128 + tid];
            if (v < bv || (v == bv && c < bi)){ bv = v; bi = c; }
        }
        idx_out[bm + tid] = bi;
    }
}

// ---------------- gather: packed fp16 zq, idx-as-float, counts, commit-loss ----------------
__global__ void vq_post(const float* __restrict__ z, const float* __restrict__ emb,
                        const int* __restrict__ idx, uint32_t* __restrict__ zqH,
                        float* __restrict__ counts, float* __restrict__ loss,
                        float* __restrict__ out_idx)
{
    int b = blockIdx.x * 256 + threadIdx.x;
    int k = idx[b];
    const float4* e  = (const float4*)(emb + (size_t)k * DLAT);
    const float4* zz = (const float4*)(z   + (size_t)b * DLAT);
    uint32_t*     zo = zqH + (size_t)b * 32;
    float s = 0.0f;
    #pragma unroll
    for (int q = 0; q < 16; q++){
        float4 ev = e[q], zv = zz[q];
        float dx = ev.x - zv.x, dy = ev.y - zv.y, dz = ev.z - zv.z, dw = ev.w - zv.w;
        s += dx*dx + dy*dy + dz*dz + dw*dw;
        zo[q*2]   = fp16_pack_hi(ev.x, ev.y);
        zo[q*2+1] = fp16_pack_hi(ev.z, ev.w);
    }
    out_idx[b] = (float)k;
    atomicAdd(&counts[k], 1.0f);

    __shared__ float red[256];
    red[threadIdx.x] = s;
    __syncthreads();
    for (int off = 128; off > 0; off >>= 1){
        if (threadIdx.x < off) red[threadIdx.x] += red[threadIdx.x + off];
        __syncthreads();
    }
    if (threadIdx.x == 0) atomicAdd(loss, red[0]);
}

// ---------------- perplexity + vq_loss scalars ----------------
__global__ void finalize_kernel(const float* __restrict__ counts, const float* __restrict__ loss,
                                float* __restrict__ out)
{
    __shared__ float red[256];
    float s = 0.0f;
    for (int k = threadIdx.x; k < KCODES; k += 256){
        float p = counts[k] * (1.0f / (float)BATCH);
        s += p * logf(p + 1e-10f);
    }
    red[threadIdx.x] = s;
    __syncthreads();
    for (int off = 128; off > 0; off >>= 1){
        if (threadIdx.x < off) red[threadIdx.x] += red[threadIdx.x + off];
        __syncthreads();
    }
    if (threadIdx.x == 0){
        out[PERP_OFF] = expf(-red[0]);
        out[LOSS_OFF] = loss[0] * (0.25f / ((float)BATCH * (float)DLAT));
    }
}

// ---------------- launch ----------------
extern "C" void kernel_launch(void* const* d_in, const int* in_sizes, int n_in,
                              void* d_out, int out_size)
{
    (void)in_sizes; (void)n_in; (void)out_size;
    const float* x   = (const float*)d_in[0];
    const float* W1  = (const float*)d_in[1];
    const float* b1  = (const float*)d_in[2];
    const float* W2  = (const float*)d_in[3];
    const float* b2  = (const float*)d_in[4];
    const float* W3  = (const float*)d_in[5];
    const float* b3  = (const float*)d_in[6];
    const float* emb = (const float*)d_in[7];
    const float* dW1 = (const float*)d_in[8];
    const float* db1 = (const float*)d_in[9];
    const float* dW2 = (const float*)d_in[10];
    const float* db2 = (const float*)d_in[11];
    const float* pW  = (const float*)d_in[12];
    const float* pb  = (const float*)d_in[13];
    const float* wW  = (const float*)d_in[14];
    const float* wb  = (const float*)d_in[15];
    const float* aW  = (const float*)d_in[16];
    const float* ab  = (const float*)d_in[17];
    float* out = (float*)d_out;

    float *z, *counts, *loss, *enorm, *hb, *b3p;
    uint32_t *xH, *xL, *w1H, *w1L, *h1H, *h1L, *w2H, *w2L, *h2H, *h2L, *w3H, *w3L;
    uint32_t *zHiT, *zLoT, *eHiT, *eLoT;
    uint32_t *zqH, *dW1H, *d1H, *dW2H, *d2H, *hwH;
    int* idx;
    cudaGetSymbolAddress((void**)&z,  g_z);
    cudaGetSymbolAddress((void**)&idx, g_idx);
    cudaGetSymbolAddress((void**)&counts, g_counts);
    cudaGetSymbolAddress((void**)&loss, g_loss);
    cudaGetSymbolAddress((void**)&enorm, g_enorm);
    cudaGetSymbolAddress((void**)&hb, g_hb);
    cudaGetSymbolAddress((void**)&b3p, g_b3p);
    cudaGetSymbolAddress((void**)&xH, g_xH);
    cudaGetSymbolAddress((void**)&xL, g_xL);
    cudaGetSymbolAddress((void**)&w1H, g_w1H);
    cudaGetSymbolAddress((void**)&w1L, g_w1L);
    cudaGetSymbolAddress((void**)&h1H, g_h1H);
    cudaGetSymbolAddress((void**)&h1L, g_h1L);
    cudaGetSymbolAddress((void**)&w2H, g_w2H);
    cudaGetSymbolAddress((void**)&w2L, g_w2L);
    cudaGetSymbolAddress((void**)&h2H, g_h2H);
    cudaGetSymbolAddress((void**)&h2L, g_h2L);
    cudaGetSymbolAddress((void**)&w3H, g_w3H);
    cudaGetSymbolAddress((void**)&w3L, g_w3L);
    cudaGetSymbolAddress((void**)&zHiT, g_zHiT);
    cudaGetSymbolAddress((void**)&zLoT, g_zLoT);
    cudaGetSymbolAddress((void**)&eHiT, g_eHiT);
    cudaGetSymbolAddress((void**)&eLoT, g_eLoT);
    cudaGetSymbolAddress((void**)&zqH,  g_zqH);
    cudaGetSymbolAddress((void**)&dW1H, g_dW1H);
    cudaGetSymbolAddress((void**)&d1H,  g_d1H);
    cudaGetSymbolAddress((void**)&dW2H, g_dW2H);
    cudaGetSymbolAddress((void**)&d2H,  g_d2H);
    cudaGetSymbolAddress((void**)&hwH,  g_hwH);

    // setup: one mega kernel (all weight packs + scalars) + wide x pack (K padded to 800)
    mega_setup<<<(S_TOTAL + 255)/256, 256>>>(
        W1, W2, W3, b3, emb, dW1, dW2, pW, pb, wW, wb, aW, ab,
        counts, loss, enorm, b3p, hb,
        w1H, w1L, w2H, w2L, w3H, w3L, eHiT, eLoT, dW1H, dW2H, hwH);
    pack_rowsA4<<<(BATCH*200 + 255)/256, 256>>>(x, xH, xL);

    // encoder (fp16-split 3-product, BK=32; enc1 K padded 784->800 with exact zeros)
    mma_gemm_f16<ACT_LEAKY, 1><<<dim3(2, BATCH/128), 256>>>(
        xH, xL, w1H, w1L, b1, nullptr, h1H, h1L, BATCH, 256, 800);
    mma_gemm_f16<ACT_LEAKY, 1><<<dim3(2, BATCH/128), 256>>>(
        h1H, h1L, w2H, w2L, b2, nullptr, h2H, h2L, BATCH, 256, 256);
    // z projection: fp16-split MMA, fused fp32 z + transposed hi/lo packs
    mma_gemm_f16<ACT_NONE, 2><<<dim3(1, BATCH/128), 256>>>(
        h2H, h2L, w3H, w3L, b3p, z, zHiT, zLoT, BATCH, 128, 256);

    // VQ
    vq_argmin_f16<<<BATCH/128, 256>>>(zHiT, zLoT, eHiT, eLoT, enorm, idx);
    vq_post<<<BATCH/256, 256>>>(z, emb, idx, zqH, counts, loss, out + IDX_OFF);
    finalize_kernel<<<1, 256>>>(counts, loss, out);

    // decoder (fp16 hi-only 1-product, BK=32)
    mma_gemm_h16<ACT_SELU, 1><<<dim3(HIDDEN/128, BATCH/128), 256>>>(
        zqH, dW1H, db1, nullptr, d1H, BATCH, HIDDEN, DLAT);
    mma_gemm_h16<ACT_SELU, 1><<<dim3(HIDDEN/128, BATCH/128), 256>>>(
        d1H, dW2H, db2, nullptr, d2H, BATCH, HIDDEN, HIDDEN);

    // head (fp16 hi-only, fused output packing straight into out)
    mma_gemm_h16<ACT_HEAD, 3><<<dim3(1, BATCH/128), 256>>>(
        d2H, hwH, hb, out, nullptr, BATCH, 128, HIDDEN);
}

// round 17
// speedup vs baseline: 1.0005x; 1.0005x over previous
#include <cuda_runtime.h>
#include <cuda_fp16.h>
#include <math.h>
#include <stdint.h>

// ---------------- problem constants ----------------
#define BATCH   32768
#define KCODES  4096
#define DLAT    64
#define HIDDEN  1024

// output layout (f32, reference return order, flattened+concat)
#define P_OFF    0
#define P_SIZE   (BATCH*40)
#define CP_OFF   (P_OFF + P_SIZE)
#define CP_SIZE  (BATCH*48)
#define W_OFF    (CP_OFF + CP_SIZE)
#define WA_SIZE  (BATCH*2)
#define A_OFF    (W_OFF + WA_SIZE)
#define LOSS_OFF (A_OFF + WA_SIZE)
#define IDX_OFF  (LOSS_OFF + 1)
#define PERP_OFF (IDX_OFF + BATCH)

#define HS 136           // VQ smem word stride (conflict-free)
#define AKP2 20          // BK32 A smem word stride (16 used + 4 pad)
#define BNP 136          // B smem word stride

// ---------------- scratch (__device__ globals; no allocation allowed) ----------------
__device__ float  g_counts[KCODES];
__device__ float  g_loss;
__device__ float  g_enorm[KCODES];
__device__ float  g_hb [128];
__device__ float  g_b3p[128];             // padded b3
// fp16-split packed operands (encoder + VQ); x/W1 padded K 784->800
__device__ uint32_t g_xH [BATCH*400];
__device__ uint32_t g_xL [BATCH*400];
__device__ uint32_t g_w1H[400*256];
__device__ uint32_t g_w1L[400*256];
__device__ uint32_t g_h1H[BATCH*128];
__device__ uint32_t g_h1L[BATCH*128];
__device__ uint32_t g_w2H[128*256];
__device__ uint32_t g_w2L[128*256];
__device__ uint32_t g_h2H[BATCH*128];
__device__ uint32_t g_h2L[BATCH*128];
__device__ uint32_t g_w3H[128*128];       // W3 padded [kp=128][n=128]
__device__ uint32_t g_w3L[128*128];
__device__ uint32_t g_zHiT[32*BATCH];
__device__ uint32_t g_zLoT[32*BATCH];
__device__ uint32_t g_eHiT[32*KCODES];
__device__ uint32_t g_eLoT[32*KCODES];
// fp16 hi-only packed (decoder)
__device__ uint32_t g_zqH [BATCH*32];
__device__ uint32_t g_dW1H[32*HIDDEN];
__device__ uint32_t g_d1H [BATCH*512];
__device__ uint32_t g_dW2H[512*HIDDEN];
__device__ uint32_t g_d2H [BATCH*512];
__device__ uint32_t g_hwH [512*128];

// ---------------- activations ----------------
#define ACT_NONE 0
#define ACT_LEAKY 1
#define ACT_SELU 2
#define ACT_HEAD 3

__device__ __forceinline__ float sigmoidf_(float x){ return 1.0f/(1.0f+expf(-x)); }

template<int ACT>
__device__ __forceinline__ float apply_act(float v, int col){
    if (ACT == ACT_LEAKY) return v > 0.0f ? v : 0.2f*v;
    if (ACT == ACT_SELU){
        const float a = 1.6732632423543772f, s = 1.0507009873554805f;
        return v > 0.0f ? s*v : s*a*(expf(v)-1.0f);
    }
    if (ACT == ACT_HEAD){
        if (col < 40) return tanhf(v)*12.0f + 14.0f;
        if (col < 42) return sigmoidf_(v)*2.0f + 1.0f;
        return sigmoidf_(v);
    }
    return v;
}

// ---------------- fp16 pack helpers ----------------
__device__ __forceinline__ void fp16_split_pack(float x0, float x1,
                                                uint32_t& hi, uint32_t& lo){
    __half h0 = __float2half_rn(x0), h1 = __float2half_rn(x1);
    __half l0 = __float2half_rn(x0 - __half2float(h0));
    __half l1 = __float2half_rn(x1 - __half2float(h1));
    __half2 hh = __halves2half2(h0, h1);
    __half2 ll = __halves2half2(l0, l1);
    hi = *(uint32_t*)&hh;
    lo = *(uint32_t*)&ll;
}
__device__ __forceinline__ uint32_t fp16_pack_hi(float x0, float x1){
    __half2 hh = __halves2half2(__float2half_rn(x0), __float2half_rn(x1));
    return *(uint32_t*)&hh;
}

// D += A*B, m16n8k16 fp16 (fp32 accum)
__device__ __forceinline__ void mma16(float* c, const uint32_t* a, const uint32_t* b){
    asm volatile(
        "mma.sync.aligned.m16n8k16.row.col.f32.f16.f16.f32 "
        "{%0,%1,%2,%3}, {%4,%5,%6,%7}, {%8,%9}, {%0,%1,%2,%3};\n"
        : "+f"(c[0]), "+f"(c[1]), "+f"(c[2]), "+f"(c[3])
        : "r"(a[0]), "r"(a[1]), "r"(a[2]), "r"(a[3]), "r"(b[0]), "r"(b[1]));
}

// ldmatrix x4: loads full m16k16 A fragment (b16) from row-major smem
__device__ __forceinline__ void ldm_x4(uint32_t* r, uint32_t addr){
    asm volatile("ldmatrix.sync.aligned.m8n8.x4.shared.b16 {%0,%1,%2,%3}, [%4];"
        : "=r"(r[0]), "=r"(r[1]), "=r"(r[2]), "=r"(r[3]) : "r"(addr));
}

// ---------------- cp.async helpers ----------------
__device__ __forceinline__ void cpasync16(void* dst_smem, const void* src){
    uint32_t s = (uint32_t)__cvta_generic_to_shared(dst_smem);
    asm volatile("cp.async.cg.shared.global [%0], [%1], 16;\n" :: "r"(s), "l"(src));
}
__device__ __forceinline__ void cpasync_commit(){ asm volatile("cp.async.commit_group;\n"); }
template<int NN>
__device__ __forceinline__ void cpasync_wait(){ asm volatile("cp.async.wait_group %0;\n" :: "n"(NN)); }

// ---------------- x pack (wide, float4/thread, K padded 784->800) ----------------
__global__ void pack_rowsA4(const float* __restrict__ src,
                            uint32_t* __restrict__ hiA, uint32_t* __restrict__ loA){
    int i = blockIdx.x * 256 + threadIdx.x;     // quad index; 200 quads per row
    if (i >= BATCH*200) return;
    int row = i / 200, q = i - row*200;
    float4 v = make_float4(0.f, 0.f, 0.f, 0.f);
    if (q < 196) v = *(const float4*)(src + (size_t)row*784 + q*4);
    uint32_t h0, l0, h1, l1;
    fp16_split_pack(v.x, v.y, h0, l0);
    fp16_split_pack(v.z, v.w, h1, l1);
    ((uint2*)hiA)[i] = make_uint2(h0, h1);
    ((uint2*)loA)[i] = make_uint2(l0, l1);
}

// ---------------- mega setup: all weight packs + scalars in ONE launch ----------------
#define S_ZERO   (KCODES + 1)                 // counts + loss
#define S_ENORM  KCODES
#define S_W1     (400*256)
#define S_W2     (128*256)
#define S_W3     (128*128)
#define S_EMBT   (32*KCODES)
#define S_DW1    (32*HIDDEN)
#define S_DW2    (512*HIDDEN)
#define S_HEAD   (512*128)
#define O_ENORM  S_ZERO
#define O_W1     (O_ENORM + S_ENORM)
#define O_W2     (O_W1 + S_W1)
#define O_W3     (O_W2 + S_W2)
#define O_EMBT   (O_W3 + S_W3)
#define O_DW1    (O_EMBT + S_EMBT)
#define O_DW2    (O_DW1 + S_DW1)
#define O_HEAD   (O_DW2 + S_DW2)
#define S_TOTAL  (O_HEAD + S_HEAD)

__device__ __forceinline__ float head_w(const float* pW, const float* wW,
                                        const float* aW, int k, int col){
    if (col < 40) return pW[k*40 + col];
    if (col < 42) return wW[k*2 + (col-40)];
    if (col < 44) return aW[k*2 + (col-42)];
    return 0.0f;
}

__global__ void mega_setup(
    const float* __restrict__ W1, const float* __restrict__ W2,
    const float* __restrict__ W3, const float* __restrict__ b3,
    const float* __restrict__ emb,
    const float* __restrict__ dW1, const float* __restrict__ dW2,
    const float* __restrict__ pW, const float* __restrict__ pb,
    const float* __restrict__ wW, const float* __restrict__ wb,
    const float* __restrict__ aW, const float* __restrict__ ab,
    float* __restrict__ counts, float* __restrict__ loss,
    float* __restrict__ enorm, float* __restrict__ b3p, float* __restrict__ hb,
    uint32_t* __restrict__ w1H, uint32_t* __restrict__ w1L,
    uint32_t* __restrict__ w2H, uint32_t* __restrict__ w2L,
    uint32_t* __restrict__ w3H, uint32_t* __restrict__ w3L,
    uint32_t* __restrict__ eHiT, uint32_t* __restrict__ eLoT,
    uint32_t* __restrict__ dW1H, uint32_t* __restrict__ dW2H,
    uint32_t* __restrict__ hwH)
{
    int gi = blockIdx.x * 256 + threadIdx.x;
    if (gi >= S_TOTAL) return;

    if (gi < S_ZERO){
        if (gi < KCODES) counts[gi] = 0.0f; else loss[0] = 0.0f;
    } else if (gi < O_W1){
        int k = gi - O_ENORM;
        const float4* e = (const float4*)(emb + (size_t)k * DLAT);
        float s = 0.0f;
        #pragma unroll
        for (int q = 0; q < 16; q++){
            float4 v = e[q];
            s += v.x*v.x + v.y*v.y + v.z*v.z + v.w*v.w;
        }
        enorm[k] = s;
    } else if (gi < O_W2){
        int i = gi - O_W1;                 // W1 pack [kp=400][n=256], kp>=392 zero
        int kp = i >> 8, n = i & 255;
        float x0 = 0.0f, x1 = 0.0f;
        if (kp < 392){
            x0 = W1[(size_t)(2*kp)*256 + n];
            x1 = W1[(size_t)(2*kp+1)*256 + n];
        }
        uint32_t hi, lo;
        fp16_split_pack(x0, x1, hi, lo);
        w1H[i] = hi; w1L[i] = lo;
    } else if (gi < O_W3){
        int i = gi - O_W2;                 // W2 pack [kp=128][n=256]
        int kp = i >> 8, n = i & 255;
        uint32_t hi, lo;
        fp16_split_pack(W2[(size_t)(2*kp)*256 + n], W2[(size_t)(2*kp+1)*256 + n], hi, lo);
        w2H[i] = hi; w2L[i] = lo;
    } else if (gi < O_EMBT){
        int i = gi - O_W3;                 // W3 padded pack [kp=128][n=128]
        int kp = i >> 7, n = i & 127;
        float x0 = 0.0f, x1 = 0.0f;
        if (n < 64){
            x0 = W3[(size_t)(2*kp)*64 + n];
            x1 = W3[(size_t)(2*kp+1)*64 + n];
        }
        uint32_t hi, lo;
        fp16_split_pack(x0, x1, hi, lo);
        w3H[i] = hi; w3L[i] = lo;
        if (i < 128) b3p[i] = (i < 64) ? b3[i] : 0.0f;
    } else if (gi < O_DW1){
        int i = gi - O_EMBT;               // embT pack [dp=32][code]
        int dp = i >> 12, c = i & (KCODES-1);
        uint32_t hi, lo;
        fp16_split_pack(emb[(size_t)c*DLAT + 2*dp], emb[(size_t)c*DLAT + 2*dp + 1], hi, lo);
        eHiT[i] = hi; eLoT[i] = lo;
    } else if (gi < O_DW2){
        int i = gi - O_DW1;                // dW1 hi pack [kp=32][n=1024]
        int kp = i >> 10, n = i & 1023;
        dW1H[i] = fp16_pack_hi(dW1[(size_t)(2*kp)*HIDDEN + n], dW1[(size_t)(2*kp+1)*HIDDEN + n]);
    } else if (gi < O_HEAD){
        int i = gi - O_DW2;                // dW2 hi pack [kp=512][n=1024]
        int kp = i >> 10, n = i & 1023;
        dW2H[i] = fp16_pack_hi(dW2[(size_t)(2*kp)*HIDDEN + n], dW2[(size_t)(2*kp+1)*HIDDEN + n]);
    } else {
        int i = gi - O_HEAD;               // head hi pack (direct) [kp=512][n=128]
        int kp = i >> 7, n = i & 127;
        float x0 = head_w(pW, wW, aW, 2*kp,   n);
        float x1 = head_w(pW, wW, aW, 2*kp+1, n);
        hwH[i] = fp16_pack_hi(x0, x1);
        if (i < 128){
            float v = 0.0f;
            if (i < 40)      v = pb[i];
            else if (i < 42) v = wb[i-40];
            else if (i < 44) v = ab[i-42];
            hb[i] = v;
        }
    }
}

// ============================================================================
// fp16-split GEMM: 3-product hi/lo. A [m][kp], B [kp][n]. BK=32, ldmatrix A.
// OUTPACK: 0 = fp32 C; 1 = packed hi/lo C;
//          2 = transposed hi/lo packs zHiT/zLoT [dp][b] only
// ============================================================================
template<int ACT, int OUTPACK>
__global__ void __launch_bounds__(256, 2) mma_gemm_f16(
    const uint32_t* __restrict__ AH, const uint32_t* __restrict__ AL,
    const uint32_t* __restrict__ BH, const uint32_t* __restrict__ BL,
    const float* __restrict__ bias, float* __restrict__ C,
    uint32_t* __restrict__ CH, uint32_t* __restrict__ CL,
    int M, int N, int K)
{
    __shared__ uint32_t AsH[2][128][AKP2], AsL[2][128][AKP2];
    __shared__ uint32_t BsH[2][16][BNP],   BsL[2][16][BNP];

    const int tid  = threadIdx.x;
    const int lane = tid & 31, warp = tid >> 5;
    const int wm = (warp & 1) * 64, wn = (warp >> 1) * 32;
    const int bm = blockIdx.y * 128, bn = blockIdx.x * 128;
    const int g = lane >> 2, tg = lane & 3;
    const int KP = K >> 1;

    // ldmatrix lane mapping: row = base + (lane&15), word col += (lane>>4)*4
    const uint32_t aHbase = (uint32_t)__cvta_generic_to_shared(&AsH[0][0][0]);
    const uint32_t aLbase = (uint32_t)__cvta_generic_to_shared(&AsL[0][0][0]);
    const int lrow = lane & 15, lcol = (lane >> 4) * 4;

    float acc[4][4][4];
    #pragma unroll
    for (int i = 0; i < 4; i++)
        #pragma unroll
        for (int j = 0; j < 4; j++)
            #pragma unroll
            for (int q = 0; q < 4; q++) acc[i][j][q] = 0.0f;

    const int ar = tid >> 1, ac = (tid & 1) * 8;
    const int br = tid >> 4, bc = (tid & 15) * 8;
    const uint32_t* AHp = AH + (size_t)(bm + ar) * KP + ac;
    const uint32_t* ALp = AL + (size_t)(bm + ar) * KP + ac;
    const uint32_t* BHp = BH + (size_t)br * N + bn + bc;
    const uint32_t* BLp = BL + (size_t)br * N + bn + bc;

    const int ntiles = K >> 5;   // 16 kp per tile

    #define COPY_F16(kt, buf) do { \
        cpasync16(&AsH[buf][ar][ac],   AHp + (size_t)(kt)*16); \
        cpasync16(&AsH[buf][ar][ac+4], AHp + (size_t)(kt)*16 + 4); \
        cpasync16(&AsL[buf][ar][ac],   ALp + (size_t)(kt)*16); \
        cpasync16(&AsL[buf][ar][ac+4], ALp + (size_t)(kt)*16 + 4); \
        cpasync16(&BsH[buf][br][bc],   BHp + (size_t)(kt)*16*N); \
        cpasync16(&BsH[buf][br][bc+4], BHp + (size_t)(kt)*16*N + 4); \
        cpasync16(&BsL[buf][br][bc],   BLp + (size_t)(kt)*16*N); \
        cpasync16(&BsL[buf][br][bc+4], BLp + (size_t)(kt)*16*N + 4); \
        cpasync_commit(); \
    } while (0)

    COPY_F16(0, 0);

    for (int i = 0; i < ntiles; i++){
        int buf = i & 1;
        if (i + 1 < ntiles){
            COPY_F16(i + 1, buf ^ 1);
            cpasync_wait<1>();
        } else {
            cpasync_wait<0>();
        }
        __syncthreads();

        #pragma unroll
        for (int kb = 0; kb < 2; kb++){
            uint32_t ah[4][4], al[4][4];
            #pragma unroll
            for (int mt = 0; mt < 4; mt++){
                uint32_t off = (uint32_t)((buf*128 + wm + mt*16 + lrow)*AKP2 + kb*8 + lcol) * 4u;
                ldm_x4(ah[mt], aHbase + off);
                ldm_x4(al[mt], aLbase + off);
            }
            #pragma unroll
            for (int nt = 0; nt < 4; nt++){
                int n = wn + nt*8 + g;
                uint32_t bh[2] = { BsH[buf][kb*8+tg][n], BsH[buf][kb*8+tg+4][n] };
                uint32_t bl[2] = { BsL[buf][kb*8+tg][n], BsL[buf][kb*8+tg+4][n] };
                #pragma unroll
                for (int mt = 0; mt < 4; mt++) mma16(acc[mt][nt], ah[mt], bh);
                #pragma unroll
                for (int mt = 0; mt < 4; mt++) mma16(acc[mt][nt], al[mt], bh);
                #pragma unroll
                for (int mt = 0; mt < 4; mt++) mma16(acc[mt][nt], ah[mt], bl);
            }
        }
        __syncthreads();
    }
    #undef COPY_F16

    #pragma unroll
    for (int mt = 0; mt < 4; mt++){
        #pragma unroll
        for (int nt = 0; nt < 4; nt++){
            int row = bm + wm + mt*16 + g;
            int col = bn + wn + nt*8 + 2*tg;
            float bs0 = bias[col], bs1 = bias[col+1];
            float v00 = apply_act<ACT>(acc[mt][nt][0] + bs0, col);
            float v01 = apply_act<ACT>(acc[mt][nt][1] + bs1, col+1);
            float v10 = apply_act<ACT>(acc[mt][nt][2] + bs0, col);
            float v11 = apply_act<ACT>(acc[mt][nt][3] + bs1, col+1);
            if (OUTPACK == 1){
                int w = col >> 1;
                int NP = N >> 1;
                uint32_t h0, l0, h1, l1;
                fp16_split_pack(v00, v01, h0, l0);
                fp16_split_pack(v10, v11, h1, l1);
                CH[(size_t)row*NP + w]     = h0;
                CL[(size_t)row*NP + w]     = l0;
                CH[(size_t)(row+8)*NP + w] = h1;
                CL[(size_t)(row+8)*NP + w] = l1;
            } else if (OUTPACK == 2){
                if (col < DLAT){
                    int dp = col >> 1;
                    uint32_t h0, l0, h1, l1;
                    fp16_split_pack(v00, v01, h0, l0);
                    fp16_split_pack(v10, v11, h1, l1);
                    CH[(size_t)dp*BATCH + row]     = h0;
                    CL[(size_t)dp*BATCH + row]     = l0;
                    CH[(size_t)dp*BATCH + row + 8] = h1;
                    CL[(size_t)dp*BATCH + row + 8] = l1;
                }
            } else {
                *(float2*)&C[(size_t)row*N + col]     = make_float2(v00, v01);
                *(float2*)&C[(size_t)(row+8)*N + col] = make_float2(v10, v11);
            }
        }
    }
}

// ============================================================================
// fp16 hi-only GEMM (decoder + head): 1-product, BK=32, ldmatrix A.
// OUTPACK: 0 = fp32 C; 1 = packed hi C; 3 = fused output packing (head)
// ============================================================================
template<int ACT, int OUTPACK>
__global__ void __launch_bounds__(256, 2) mma_gemm_h16(
    const uint32_t* __restrict__ AH, const uint32_t* __restrict__ BH,
    const float* __restrict__ bias, float* __restrict__ C,
    uint32_t* __restrict__ CH,
    int M, int N, int K)
{
    __shared__ uint32_t AsH[2][128][AKP2];
    __shared__ uint32_t BsH[2][16][BNP];

    const int tid  = threadIdx.x;
    const int lane = tid & 31, warp = tid >> 5;
    const int wm = (warp & 1) * 64, wn = (warp >> 1) * 32;
    const int bm = blockIdx.y * 128, bn = blockIdx.x * 128;
    const int g = lane >> 2, tg = lane & 3;
    const int KP = K >> 1;

    const uint32_t aHbase = (uint32_t)__cvta_generic_to_shared(&AsH[0][0][0]);
    const int lrow = lane & 15, lcol = (lane >> 4) * 4;

    float acc[4][4][4];
    #pragma unroll
    for (int i = 0; i < 4; i++)
        #pragma unroll
        for (int j = 0; j < 4; j++)
            #pragma unroll
            for (int q = 0; q < 4; q++) acc[i][j][q] = 0.0f;

    const int ar = tid >> 1, ac = (tid & 1) * 8;
    const int br = tid >> 4, bc = (tid & 15) * 8;
    const uint32_t* AHp = AH + (size_t)(bm + ar) * KP + ac;
    const uint32_t* BHp = BH + (size_t)br * N + bn + bc;

    const int ntiles = K >> 5;   // 16 kp per tile

    #define COPY_H16(kt, buf) do { \
        cpasync16(&AsH[buf][ar][ac],   AHp + (size_t)(kt)*16); \
        cpasync16(&AsH[buf][ar][ac+4], AHp + (size_t)(kt)*16 + 4); \
        cpasync16(&BsH[buf][br][bc],   BHp + (size_t)(kt)*16*N); \
        cpasync16(&BsH[buf][br][bc+4], BHp + (size_t)(kt)*16*N + 4); \
        cpasync_commit(); \
    } while (0)

    COPY_H16(0, 0);

    for (int i = 0; i < ntiles; i++){
        int buf = i & 1;
        if (i + 1 < ntiles){
            COPY_H16(i + 1, buf ^ 1);
            cpasync_wait<1>();
        } else {
            cpasync_wait<0>();
        }
        __syncthreads();

        #pragma unroll
        for (int kb = 0; kb < 2; kb++){
            uint32_t ah[4][4];
            #pragma unroll
            for (int mt = 0; mt < 4; mt++){
                uint32_t off = (uint32_t)((buf*128 + wm + mt*16 + lrow)*AKP2 + kb*8 + lcol) * 4u;
                ldm_x4(ah[mt], aHbase + off);
            }
            #pragma unroll
            for (int nt = 0; nt < 4; nt++){
                int n = wn + nt*8 + g;
                uint32_t bh[2] = { BsH[buf][kb*8+tg][n], BsH[buf][kb*8+tg+4][n] };
                #pragma unroll
                for (int mt = 0; mt < 4; mt++) mma16(acc[mt][nt], ah[mt], bh);
            }
        }
        __syncthreads();
    }
    #undef COPY_H16

    #pragma unroll
    for (int mt = 0; mt < 4; mt++){
        #pragma unroll
        for (int nt = 0; nt < 4; nt++){
            int row = bm + wm + mt*16 + g;
            int col = bn + wn + nt*8 + 2*tg;
            float bs0 = bias[col], bs1 = bias[col+1];
            float v00 = apply_act<ACT>(acc[mt][nt][0] + bs0, col);
            float v01 = apply_act<ACT>(acc[mt][nt][1] + bs1, col+1);
            float v10 = apply_act<ACT>(acc[mt][nt][2] + bs0, col);
            float v11 = apply_act<ACT>(acc[mt][nt][3] + bs1, col+1);
            if (OUTPACK == 1){
                int w = col >> 1;
                int NP = N >> 1;
                CH[(size_t)row*NP + w]     = fp16_pack_hi(v00, v01);
                CH[(size_t)(row+8)*NP + w] = fp16_pack_hi(v10, v11);
            } else if (OUTPACK == 3){
                // fused output packing (head): col even, valid cols < 44
                if (col < 40){
                    int p = col / 20, rem = col - p*20;
                    int q = rem >> 1;
                    *(float2*)&C[P_OFF + (size_t)row*40 + col]     = make_float2(v00, v01);
                    *(float2*)&C[P_OFF + (size_t)(row+8)*40 + col] = make_float2(v10, v11);
                    #pragma unroll
                    for (int sg = 0; sg < 3; sg++){
                        int j = q - 3*sg;
                        if (j >= 0 && j < 4){
                            size_t o = (size_t)p*24 + sg*8 + j*2;
                            *(float2*)&C[CP_OFF + (size_t)row*48 + o]     = make_float2(v00, v01);
                            *(float2*)&C[CP_OFF + (size_t)(row+8)*48 + o] = make_float2(v10, v11);
                        }
                    }
                } else if (col == 40){
                    *(float2*)&C[W_OFF + (size_t)row*2]     = make_float2(v00, v01);
                    *(float2*)&C[W_OFF + (size_t)(row+8)*2] = make_float2(v10, v11);
                } else if (col == 42){
                    *(float2*)&C[A_OFF + (size_t)row*2]     = make_float2(v00, v01);
                    *(float2*)&C[A_OFF + (size_t)(row+8)*2] = make_float2(v10, v11);
                }
            } else {
                *(float2*)&C[(size_t)row*N + col]     = make_float2(v00, v01);
                *(float2*)&C[(size_t)(row+8)*N + col] = make_float2(v10, v11);
            }
        }
    }
}

// ---------------- VQ argmin + fused post: fp16-split m16n8k16 ----------------
// After the argmin, each of the first 128 threads owns row bm+tid: gathers
// emb[bi], writes packed zqH, out_idx, counts atomic, and commit-loss partial
// (z reconstructed exactly as hi+lo from resident smem).
__global__ void __launch_bounds__(256, 2) vq_argmin_f16(
    const uint32_t* __restrict__ zHiT, const uint32_t* __restrict__ zLoT,
    const uint32_t* __restrict__ eHiT, const uint32_t* __restrict__ eLoT,
    const float* __restrict__ enorm, const float* __restrict__ emb,
    uint32_t* __restrict__ zqH, float* __restrict__ counts,
    float* __restrict__ loss, float* __restrict__ out_idx)
{
    __shared__ uint32_t ZH[32][HS], ZL[32][HS];
    __shared__ uint32_t EH[2][32][HS], EL[2][32][HS];

    const int tid  = threadIdx.x;
    const int lane = tid & 31, warp = tid >> 5;
    const int wm = (warp & 1) * 64, wn = (warp >> 1) * 32;
    const int bm = blockIdx.x * 128;
    const int g = lane >> 2, tg = lane & 3;

    {
        #pragma unroll
        for (int j = 0; j < 4; j++){
            int unit = j*256 + tid;
            int dp = unit >> 5, u = unit & 31;
            cpasync16(&ZH[dp][u*4], zHiT + (size_t)dp*BATCH + bm + u*4);
            cpasync16(&ZL[dp][u*4], zLoT + (size_t)dp*BATCH + bm + u*4);
        }
        cpasync_commit();
    }

    #define COPY_EP(c0_, buf_) do { \
        _Pragma("unroll") \
        for (int j = 0; j < 4; j++){ \
            int unit = j*256 + tid; \
            int dp_ = unit >> 5, u_ = unit & 31; \
            cpasync16(&EH[buf_][dp_][u_*4], eHiT + (size_t)dp_*KCODES + (c0_) + u_*4); \
            cpasync16(&EL[buf_][dp_][u_*4], eLoT + (size_t)dp_*KCODES + (c0_) + u_*4); \
        } \
        cpasync_commit(); \
    } while (0)

    float mv[8]; int mi[8];
    #pragma unroll
    for (int s = 0; s < 8; s++){ mv[s] = INFINITY; mi[s] = 0; }

    COPY_EP(0, 0);

    for (int ch = 0; ch < KCODES/128; ch++){
        int c0 = ch * 128;
        int buf = ch & 1;
        if (ch + 1 < KCODES/128){
            COPY_EP(c0 + 128, buf ^ 1);
            cpasync_wait<1>();
        } else {
            cpasync_wait<0>();
        }
        __syncthreads();

        float acc[4][4][4];
        #pragma unroll
        for (int i = 0; i < 4; i++)
            #pragma unroll
            for (int j = 0; j < 4; j++)
                #pragma unroll
                for (int q = 0; q < 4; q++) acc[i][j][q] = 0.0f;

        #pragma unroll
        for (int kb = 0; kb < 4; kb++){
            uint32_t ah[4][4], al[4][4];
            #pragma unroll
            for (int mt = 0; mt < 4; mt++){
                int m = wm + mt*16 + g;
                ah[mt][0] = ZH[kb*8+tg  ][m];
                ah[mt][1] = ZH[kb*8+tg  ][m+8];
                ah[mt][2] = ZH[kb*8+tg+4][m];
                ah[mt][3] = ZH[kb*8+tg+4][m+8];
                al[mt][0] = ZL[kb*8+tg  ][m];
                al[mt][1] = ZL[kb*8+tg  ][m+8];
                al[mt][2] = ZL[kb*8+tg+4][m];
                al[mt][3] = ZL[kb*8+tg+4][m+8];
            }
            #pragma unroll
            for (int nt = 0; nt < 4; nt++){
                int n = wn + nt*8 + g;
                uint32_t bh[2] = { EH[buf][kb*8+tg][n], EH[buf][kb*8+tg+4][n] };
                uint32_t bl[2] = { EL[buf][kb*8+tg][n], EL[buf][kb*8+tg+4][n] };
                #pragma unroll
                for (int mt = 0; mt < 4; mt++) mma16(acc[mt][nt], ah[mt], bh);
                #pragma unroll
                for (int mt = 0; mt < 4; mt++) mma16(acc[mt][nt], al[mt], bh);
                #pragma unroll
                for (int mt = 0; mt < 4; mt++) mma16(acc[mt][nt], ah[mt], bl);
            }
        }

        #pragma unroll
        for (int nt = 0; nt < 4; nt++){
            int nc = wn + nt*8 + 2*tg;
            float e0 = __ldg(enorm + c0 + nc);
            float e1 = __ldg(enorm + c0 + nc + 1);
            int code = c0 + nc;
            #pragma unroll
            for (int mt = 0; mt < 4; mt++){
                float d00 = e0 - 2.0f*acc[mt][nt][0];
                float d01 = e1 - 2.0f*acc[mt][nt][1];
                float d10 = e0 - 2.0f*acc[mt][nt][2];
                float d11 = e1 - 2.0f*acc[mt][nt][3];
                int s0 = mt*2, s1 = mt*2 + 1;
                if (d00 < mv[s0]){ mv[s0] = d00; mi[s0] = code;   }
                if (d01 < mv[s0]){ mv[s0] = d01; mi[s0] = code+1; }
                if (d10 < mv[s1]){ mv[s1] = d10; mi[s1] = code;   }
                if (d11 < mv[s1]){ mv[s1] = d11; mi[s1] = code+1; }
            }
        }
        __syncthreads();
    }
    #undef COPY_EP

    float* rv = (float*)&EH[0][0][0];
    int*   ri = ((int*)rv) + 16*128;
    int cand = (warp >> 1) * 4 + tg;
    #pragma unroll
    for (int s = 0; s < 8; s++){
        int r = wm + (s >> 1)*16 + g + (s & 1)*8;
        rv[cand*128 + r] = mv[s];
        ri[cand*128 + r] = mi[s];
    }
    __syncthreads();

    // fused post: argmin -> gather/pack/counts/loss
    float s_loss = 0.0f;
    if (tid < 128){
        float bv = INFINITY; int bi = 0x7fffffff;
        #pragma unroll
        for (int t = 0; t < 16; t++){
            float v = rv[t*128 + tid];
            int c = ri[t*128 + tid];
            if (v < bv || (v == bv && c < bi)){ bv = v; bi = c; }
        }
        int r = tid;
        const float4* e = (const float4*)(emb + (size_t)bi * DLAT);
        uint32_t* zo = zqH + (size_t)(bm + r) * 32;
        #pragma unroll
        for (int q = 0; q < 16; q++){
            float4 ev = e[q];
            uint32_t wh0 = ZH[2*q][r],   wl0 = ZL[2*q][r];
            uint32_t wh1 = ZH[2*q+1][r], wl1 = ZL[2*q+1][r];
            __half2 h0 = *(__half2*)&wh0, l0 = *(__half2*)&wl0;
            __half2 h1 = *(__half2*)&wh1, l1 = *(__half2*)&wl1;
            float z0 = __low2float(h0)  + __low2float(l0);
            float z1 = __high2float(h0) + __high2float(l0);
            float z2 = __low2float(h1)  + __low2float(l1);
            float z3 = __high2float(h1) + __high2float(l1);
            float dx = ev.x - z0, dy = ev.y - z1, dz = ev.z - z2, dw = ev.w - z3;
            s_loss += dx*dx + dy*dy + dz*dz + dw*dw;
            zo[q*2]   = fp16_pack_hi(ev.x, ev.y);
            zo[q*2+1] = fp16_pack_hi(ev.z, ev.w);
        }
        out_idx[bm + r] = (float)bi;
        atomicAdd(&counts[bi], 1.0f);
    }

    float* red = (float*)&EL[0][0][0];
    red[tid] = s_loss;
    __syncthreads();
    for (int off = 128; off > 0; off >>= 1){
        if (tid < off) red[tid] += red[tid + off];
        __syncthreads();
    }
    if (tid == 0) atomicAdd(loss, red[0]);
}

// ---------------- perplexity + vq_loss scalars ----------------
__global__ void finalize_kernel(const float* __restrict__ counts, const float* __restrict__ loss,
                                float* __restrict__ out)
{
    __shared__ float red[256];
    float s = 0.0f;
    for (int k = threadIdx.x; k < KCODES; k += 256){
        float p = counts[k] * (1.0f / (float)BATCH);
        s += p * logf(p + 1e-10f);
    }
    red[threadIdx.x] = s;
    __syncthreads();
    for (int off = 128; off > 0; off >>= 1){
        if (threadIdx.x < off) red[threadIdx.x] += red[threadIdx.x + off];
        __syncthreads();
    }
    if (threadIdx.x == 0){
        out[PERP_OFF] = expf(-red[0]);
        out[LOSS_OFF] = loss[0] * (0.25f / ((float)BATCH * (float)DLAT));
    }
}

// ---------------- launch ----------------
extern "C" void kernel_launch(void* const* d_in, const int* in_sizes, int n_in,
                              void* d_out, int out_size)
{
    (void)in_sizes; (void)n_in; (void)out_size;
    const float* x   = (const float*)d_in[0];
    const float* W1  = (const float*)d_in[1];
    const float* b1  = (const float*)d_in[2];
    const float* W2  = (const float*)d_in[3];
    const float* b2  = (const float*)d_in[4];
    const float* W3  = (const float*)d_in[5];
    const float* b3  = (const float*)d_in[6];
    const float* emb = (const float*)d_in[7];
    const float* dW1 = (const float*)d_in[8];
    const float* db1 = (const float*)d_in[9];
    const float* dW2 = (const float*)d_in[10];
    const float* db2 = (const float*)d_in[11];
    const float* pW  = (const float*)d_in[12];
    const float* pb  = (const float*)d_in[13];
    const float* wW  = (const float*)d_in[14];
    const float* wb  = (const float*)d_in[15];
    const float* aW  = (const float*)d_in[16];
    const float* ab  = (const float*)d_in[17];
    float* out = (float*)d_out;

    float *counts, *loss, *enorm, *hb, *b3p;
    uint32_t *xH, *xL, *w1H, *w1L, *h1H, *h1L, *w2H, *w2L, *h2H, *h2L, *w3H, *w3L;
    uint32_t *zHiT, *zLoT, *eHiT, *eLoT;
    uint32_t *zqH, *dW1H, *d1H, *dW2H, *d2H, *hwH;
    cudaGetSymbolAddress((void**)&counts, g_counts);
    cudaGetSymbolAddress((void**)&loss, g_loss);
    cudaGetSymbolAddress((void**)&enorm, g_enorm);
    cudaGetSymbolAddress((void**)&hb, g_hb);
    cudaGetSymbolAddress((void**)&b3p, g_b3p);
    cudaGetSymbolAddress((void**)&xH, g_xH);
    cudaGetSymbolAddress((void**)&xL, g_xL);
    cudaGetSymbolAddress((void**)&w1H, g_w1H);
    cudaGetSymbolAddress((void**)&w1L, g_w1L);
    cudaGetSymbolAddress((void**)&h1H, g_h1H);
    cudaGetSymbolAddress((void**)&h1L, g_h1L);
    cudaGetSymbolAddress((void**)&w2H, g_w2H);
    cudaGetSymbolAddress((void**)&w2L, g_w2L);
    cudaGetSymbolAddress((void**)&h2H, g_h2H);
    cudaGetSymbolAddress((void**)&h2L, g_h2L);
    cudaGetSymbolAddress((void**)&w3H, g_w3H);
    cudaGetSymbolAddress((void**)&w3L, g_w3L);
    cudaGetSymbolAddress((void**)&zHiT, g_zHiT);
    cudaGetSymbolAddress((void**)&zLoT, g_zLoT);
    cudaGetSymbolAddress((void**)&eHiT, g_eHiT);
    cudaGetSymbolAddress((void**)&eLoT, g_eLoT);
    cudaGetSymbolAddress((void**)&zqH,  g_zqH);
    cudaGetSymbolAddress((void**)&dW1H, g_dW1H);
    cudaGetSymbolAddress((void**)&d1H,  g_d1H);
    cudaGetSymbolAddress((void**)&dW2H, g_dW2H);
    cudaGetSymbolAddress((void**)&d2H,  g_d2H);
    cudaGetSymbolAddress((void**)&hwH,  g_hwH);

    // setup: one mega kernel (all weight packs + scalars) + wide x pack (K padded to 800)
    mega_setup<<<(S_TOTAL + 255)/256, 256>>>(
        W1, W2, W3, b3, emb, dW1, dW2, pW, pb, wW, wb, aW, ab,
        counts, loss, enorm, b3p, hb,
        w1H, w1L, w2H, w2L, w3H, w3L, eHiT, eLoT, dW1H, dW2H, hwH);
    pack_rowsA4<<<(BATCH*200 + 255)/256, 256>>>(x, xH, xL);

    // encoder (fp16-split 3-product, BK=32, ldmatrix A)
    mma_gemm_f16<ACT_LEAKY, 1><<<dim3(2, BATCH/128), 256>>>(
        xH, xL, w1H, w1L, b1, nullptr, h1H, h1L, BATCH, 256, 800);
    mma_gemm_f16<ACT_LEAKY, 1><<<dim3(2, BATCH/128), 256>>>(
        h1H, h1L, w2H, w2L, b2, nullptr, h2H, h2L, BATCH, 256, 256);
    // z projection: fp16-split MMA, writes transposed hi/lo packs directly
    mma_gemm_f16<ACT_NONE, 2><<<dim3(1, BATCH/128), 256>>>(
        h2H, h2L, w3H, w3L, b3p, nullptr, zHiT, zLoT, BATCH, 128, 256);

    // VQ (argmin + fused gather/pack/counts/loss)
    vq_argmin_f16<<<BATCH/128, 256>>>(zHiT, zLoT, eHiT, eLoT, enorm, emb,
                                      zqH, counts, loss, out + IDX_OFF);
    finalize_kernel<<<1, 256>>>(counts, loss, out);

    // decoder (fp16 hi-only 1-product, BK=32, ldmatrix A)
    mma_gemm_h16<ACT_SELU, 1><<<dim3(HIDDEN/128, BATCH/128), 256>>>(
        zqH, dW1H, db1, nullptr, d1H, BATCH, HIDDEN, DLAT);
    mma_gemm_h16<ACT_SELU, 1><<<dim3(HIDDEN/128, BATCH/128), 256>>>(
        d1H, dW2H, db2, nullptr, d2H, BATCH, HIDDEN, HIDDEN);

    // head (fp16 hi-only, fused output packing straight into out)
    mma_gemm_h16<ACT_HEAD, 3><<<dim3(1, BATCH/128), 256>>>(
        d2H, hwH, hb, out, nullptr, BATCH, 128, HIDDEN);
}